// round 16
// baseline (speedup 1.0000x reference)
#include <cuda_runtime.h>
#include <cstdint>

#define NB       4
#define NN       2048
#define CLAMP_V  10.0f

typedef unsigned long long ull;

// Partial G (8 d-slices): [8][NB*NN][32] floats = 8 MB (no allocs allowed)
__device__ __align__(16) float g_Gp[8 * NB * NN * 32];
// Reduced G + row squared-norms
__device__ __align__(16) float g_G[NB * NN * 32];
__device__ __align__(16) float g_Gsq[NB * NN];

// ---------------- packed f32x2 helpers (FFMA2 via PTX) ----------------
__device__ __forceinline__ ull ffma2(ull a, ull b, ull c) {
    ull d;
    asm("fma.rn.f32x2 %0, %1, %2, %3;" : "=l"(d) : "l"(a), "l"(b), "l"(c));
    return d;
}
__device__ __forceinline__ ull pack2(float x, float y) {
    ull r;
    asm("mov.b64 %0, {%1, %2};" : "=l"(r) : "f"(x), "f"(y));
    return r;
}
__device__ __forceinline__ float2 unpack2(ull v) {
    float2 f;
    asm("mov.b64 {%0, %1}, %2;" : "=f"(f.x), "=f"(f.y) : "l"(v));
    return f;
}
__device__ __forceinline__ float hadd2(ull v) {
    float2 f = unpack2(v);
    return f.x + f.y;
}
__device__ __forceinline__ uint32_t smem_u32(const void* p) {
    uint32_t a;
    asm("{ .reg .u64 t; cvta.to.shared.u64 t, %1; cvt.u32.u64 %0, t; }" : "=r"(a) : "l"(p));
    return a;
}
__device__ __forceinline__ void cp16(uint32_t dst, const void* src) {
    asm volatile("cp.async.cg.shared.global [%0], [%1], 16;" :: "r"(dst), "l"(src) : "memory");
}
#define CP_COMMIT() asm volatile("cp.async.commit_group;" ::: "memory")
#define CP_WAIT0()  asm volatile("cp.async.wait_group 0;" ::: "memory")

// ============================================================================
// Kernel 1 (R14 best, 22.3us): partial G[s][n][k], slice s = 128 d.
// 512 blocks (64 row-tiles x 8 d-slices) x 256 threads; micro 4 rows x 4 k.
// ============================================================================
#define HROW 18   // ull per H row (16 dpairs + pad 2)
#define WROW 34   // ull per Ws row (32 k + pad 2)

__global__ __launch_bounds__(256)
void geom_proj_kernel(const float* __restrict__ H, const float* __restrict__ W) {
    __shared__ ull Hs[2][128][HROW];
    __shared__ ull Ws[2][16][WROW];

    const int tid   = threadIdx.x;
    const int kg    = tid & 7;         // k = kg + 8q
    const int ty    = tid >> 3;        // rows ty + 32*r  (0..31)
    const int slice = blockIdx.x & 7;
    const int n0    = (blockIdx.x >> 3) * 128;
    const int dbase = slice * 128;     // float offset (128 d per slice)

    const float4* __restrict__ W4 = (const float4*)W;
    const uint32_t hsb = smem_u32(&Hs[0][0][0]);

    #pragma unroll
    for (int p = 0; p < 4; p++) {
        int idx = tid + 256 * p;       // 0..1023
        int row = idx >> 3, fc = idx & 7;
        cp16(hsb + (uint32_t)(row * HROW + fc * 2) * 8,
             H + (size_t)(n0 + row) * 1024 + dbase + fc * 4);
    }
    CP_COMMIT();

    float4 wr = W4[(tid >> 3) * 256 + slice * 32 + (tid & 7)];

    ull acc[4][4];
    #pragma unroll
    for (int r = 0; r < 4; r++)
        #pragma unroll
        for (int q = 0; q < 4; q++) acc[r][q] = 0ULL;

    #pragma unroll 1
    for (int c = 0; c < 4; c++) {
        const int buf = c & 1;
        CP_WAIT0();
        __syncthreads();

        {
            int k = tid >> 3, fs = tid & 7;
            Ws[buf][fs * 2][k]     = pack2(wr.x, wr.y);
            Ws[buf][fs * 2 + 1][k] = pack2(wr.z, wr.w);
        }

        if (c < 3) {
            #pragma unroll
            for (int p = 0; p < 4; p++) {
                int idx = tid + 256 * p;
                int row = idx >> 3, fc = idx & 7;
                cp16(hsb + (uint32_t)(((1 - buf) * 128 + row) * HROW + fc * 2) * 8,
                     H + (size_t)(n0 + row) * 1024 + dbase + (c + 1) * 32 + fc * 4);
            }
            CP_COMMIT();
            wr = W4[(tid >> 3) * 256 + slice * 32 + (c + 1) * 8 + (tid & 7)];
        }
        __syncthreads();

        #pragma unroll
        for (int dp2 = 0; dp2 < 8; dp2++) {
            ull w0[4], w1[4];
            #pragma unroll
            for (int q = 0; q < 4; q++) {
                w0[q] = Ws[buf][2 * dp2][kg + 8 * q];
                w1[q] = Ws[buf][2 * dp2 + 1][kg + 8 * q];
            }
            #pragma unroll
            for (int r = 0; r < 4; r++) {
                float4 hv = *(const float4*)&Hs[buf][ty + 32 * r][2 * dp2];
                ull hA = pack2(hv.x, hv.y);
                ull hB = pack2(hv.z, hv.w);
                #pragma unroll
                for (int q = 0; q < 4; q++) {
                    acc[r][q] = ffma2(hA, w0[q], acc[r][q]);
                    acc[r][q] = ffma2(hB, w1[q], acc[r][q]);
                }
            }
        }
    }

    float* __restrict__ Gp = g_Gp + (size_t)slice * (NB * NN * 32);
    #pragma unroll
    for (int r = 0; r < 4; r++) {
        const size_t rb = (size_t)(n0 + ty + 32 * r) * 32;
        #pragma unroll
        for (int q = 0; q < 4; q++)
            Gp[rb + kg + 8 * q] = hadd2(acc[r][q]);
    }
}

// ============================================================================
// Kernel 1.5: reduce the 8 d-slice partials -> g_G, and compute g_Gsq.
// ============================================================================
__global__ __launch_bounds__(128)
void reduce_g_kernel() {
    const int tid = threadIdx.x;
    const int row = blockIdx.x * 32 + (tid >> 2);   // global row 0..8191
    const int fq  = tid & 3;

    const float4* __restrict__ P = (const float4*)g_Gp;
    const size_t stride = (size_t)(NB * NN * 32) / 4;   // float4 units per slice
    float4* __restrict__ Go = (float4*)g_G;

    float sq = 0.f;
    #pragma unroll
    for (int h = 0; h < 2; h++) {
        const size_t idx = (size_t)row * 8 + fq + 4 * h;
        float4 s = P[idx];
        #pragma unroll
        for (int sl = 1; sl < 8; sl++) {
            float4 a = P[idx + sl * stride];
            s.x += a.x; s.y += a.y; s.z += a.z; s.w += a.w;
        }
        Go[idx] = s;
        sq += s.x * s.x + s.y * s.y + s.z * s.z + s.w * s.w;
    }
    sq += __shfl_xor_sync(0xFFFFFFFF, sq, 1);
    sq += __shfl_xor_sync(0xFFFFFFFF, sq, 2);
    if (fq == 0) g_Gsq[row] = sq;
}

// ============================================================================
// Kernel 2: triangular-symmetric EMA update, 256 threads (8 warps/CTA).
// Grid (528, 4); 64x64 tile; Gram micro 4(i) x 4(j) -> per-warp work halved,
// warps/SMSP doubled vs the 128-thread version (issue-duty fix).
// ============================================================================
#define GROW 18    // 16 kpairs + pad 2

__global__ __launch_bounds__(256)
void bias_update_kernel(const float* __restrict__ Bprev,
                        const float* __restrict__ alpha_p,
                        const float* __restrict__ beta_p,
                        float* __restrict__ Out) {
    __shared__ __align__(16) unsigned char gbuf[2][9216];  // Gi | Gj; later dist_t
    __shared__ __align__(16) float dist_s[64][68];
    __shared__ float gsqI[64];
    __shared__ float gsqJ[64];

    ull (*Gi)[GROW] = (ull(*)[GROW])gbuf[0];
    ull (*Gj)[GROW] = (ull(*)[GROW])gbuf[1];
    float (*dist_t)[68] = (float(*)[68])gbuf;              // 64*68*4 = 17408 <= 18432

    const int tid = threadIdx.x;
    const int tx  = tid & 15;      // Gram: j = tx + 16*jj
    const int ty  = tid >> 4;      // Gram: i = ty + 16*ii   (0..15)
    const int b   = blockIdx.y;

    // triangular decode: q -> (ti, tj), tj <= ti
    const int q = blockIdx.x;
    int ti = (int)((sqrtf(8.0f * (float)q + 1.0f) - 1.0f) * 0.5f);
    while ((ti + 1) * (ti + 2) / 2 <= q) ti++;
    while (ti * (ti + 1) / 2 > q) ti--;
    const int tj = q - ti * (ti + 1) / 2;
    const int i0 = ti * 64;
    const int j0 = tj * 64;
    const bool offd = (ti != tj);

    // ---- stage G tiles + precomputed Gsq
    const float4* __restrict__ G4 = (const float4*)g_G;
    const size_t baseI = ((size_t)b * NN + i0) * 8;   // float4 units (8/row)
    const size_t baseJ = ((size_t)b * NN + j0) * 8;

    #pragma unroll
    for (int p = 0; p < 2; p++) {
        int idx = tid + 256 * p;               // 0..511
        int row = idx >> 3, fc = idx & 7;
        float4 a = G4[baseI + idx];
        *(float4*)&Gi[row][fc * 2] = a;
        float4 c = G4[baseJ + idx];
        *(float4*)&Gj[row][fc * 2] = c;
    }
    if (tid < 64)                 gsqI[tid]      = g_Gsq[(size_t)b * NN + i0 + tid];
    else if (tid < 128)           gsqJ[tid - 64] = g_Gsq[(size_t)b * NN + j0 + (tid - 64)];
    __syncthreads();

    // ---- 4x4 Gram micro-tile
    ull acc[4][4];
    #pragma unroll
    for (int ii = 0; ii < 4; ii++)
        #pragma unroll
        for (int jj = 0; jj < 4; jj++) acc[ii][jj] = 0ULL;

    #pragma unroll
    for (int kk2 = 0; kk2 < 8; kk2++) {
        ull a0[4], a1[4], b0[4], b1[4];
        #pragma unroll
        for (int ii = 0; ii < 4; ii++) {
            float4 t = *(const float4*)&Gi[ty + 16 * ii][kk2 * 2];
            a0[ii] = pack2(t.x, t.y);
            a1[ii] = pack2(t.z, t.w);
        }
        #pragma unroll
        for (int jj = 0; jj < 4; jj++) {
            float4 t = *(const float4*)&Gj[tx + 16 * jj][kk2 * 2];
            b0[jj] = pack2(t.x, t.y);
            b1[jj] = pack2(t.z, t.w);
        }
        #pragma unroll
        for (int ii = 0; ii < 4; ii++)
            #pragma unroll
            for (int jj = 0; jj < 4; jj++) {
                acc[ii][jj] = ffma2(a0[ii], b0[jj], acc[ii][jj]);
                acc[ii][jj] = ffma2(a1[ii], b1[jj], acc[ii][jj]);
            }
    }

    const float alpha = __ldg(alpha_p);
    const float beta  = __ldg(beta_p);

    // ---- Phase B: bd = beta*max(dist,0) into registers
    float bd[4][4];
    #pragma unroll
    for (int ii = 0; ii < 4; ii++) {
        const float si = gsqI[ty + 16 * ii];
        #pragma unroll
        for (int jj = 0; jj < 4; jj++) {
            float g = hadd2(acc[ii][jj]);
            float dist = si + gsqJ[tx + 16 * jj] - 2.0f * g;
            bd[ii][jj] = beta * fmaxf(dist, 0.0f);
        }
    }
    __syncthreads();               // all Gram smem reads done (dist_t aliases G)

    #pragma unroll
    for (int ii = 0; ii < 4; ii++) {
        const int il = ty + 16 * ii;
        #pragma unroll
        for (int jj = 0; jj < 4; jj++) {
            const int jl = tx + 16 * jj;
            dist_s[il][jl] = bd[ii][jj];
            if (offd) dist_t[jl][il] = bd[ii][jj];
        }
    }
    __syncthreads();

    // ---- Phase C: vectorized epilogue; all loads batched (MLP up to 8)
    const int c4 = tid & 15;       // float4 column
    const int rg = tid >> 4;       // row = rg + 16*rr
    const size_t obase = (size_t)b * NN * NN;

    float4 bp1[4], bp2[4];
    #pragma unroll
    for (int rr = 0; rr < 4; rr++) {
        const int row = rg + 16 * rr;
        bp1[rr] = __ldg((const float4*)(Bprev + obase + (size_t)(i0 + row) * NN + j0 + 4 * c4));
    }
    if (offd) {
        #pragma unroll
        for (int rr = 0; rr < 4; rr++) {
            const int row = rg + 16 * rr;
            bp2[rr] = __ldg((const float4*)(Bprev + obase + (size_t)(j0 + row) * NN + i0 + 4 * c4));
        }
    }

    #pragma unroll
    for (int rr = 0; rr < 4; rr++) {
        const int row = rg + 16 * rr;
        float4 d = *(const float4*)&dist_s[row][4 * c4];
        float4 v;
        v.x = fminf(fmaxf(fmaf(alpha, bp1[rr].x, -d.x), -CLAMP_V), CLAMP_V);
        v.y = fminf(fmaxf(fmaf(alpha, bp1[rr].y, -d.y), -CLAMP_V), CLAMP_V);
        v.z = fminf(fmaxf(fmaf(alpha, bp1[rr].z, -d.z), -CLAMP_V), CLAMP_V);
        v.w = fminf(fmaxf(fmaf(alpha, bp1[rr].w, -d.w), -CLAMP_V), CLAMP_V);
        *(float4*)(Out + obase + (size_t)(i0 + row) * NN + j0 + 4 * c4) = v;
    }
    if (offd) {
        #pragma unroll
        for (int rr = 0; rr < 4; rr++) {
            const int row = rg + 16 * rr;
            float4 d = *(const float4*)&dist_t[row][4 * c4];
            float4 v;
            v.x = fminf(fmaxf(fmaf(alpha, bp2[rr].x, -d.x), -CLAMP_V), CLAMP_V);
            v.y = fminf(fmaxf(fmaf(alpha, bp2[rr].y, -d.y), -CLAMP_V), CLAMP_V);
            v.z = fminf(fmaxf(fmaf(alpha, bp2[rr].z, -d.z), -CLAMP_V), CLAMP_V);
            v.w = fminf(fmaxf(fmaf(alpha, bp2[rr].w, -d.w), -CLAMP_V), CLAMP_V);
            *(float4*)(Out + obase + (size_t)(j0 + row) * NN + i0 + 4 * c4) = v;
        }
    }
}

// ============================================================================
extern "C" void kernel_launch(void* const* d_in, const int* in_sizes, int n_in,
                              void* d_out, int out_size) {
    const float* H     = (const float*)d_in[0];   // [4,2048,1024]
    const float* Bprev = (const float*)d_in[1];   // [4,2048,2048]
    const float* W     = (const float*)d_in[2];   // [32,1024]
    const float* alpha = (const float*)d_in[3];   // scalar
    const float* beta  = (const float*)d_in[4];   // scalar
    float* Out = (float*)d_out;

    geom_proj_kernel<<<512, 256>>>(H, W);
    reduce_g_kernel<<<256, 128>>>();
    bias_update_kernel<<<dim3(528, NB), 256>>>(Bprev, alpha, beta, Out);
}

// round 17
// speedup vs baseline: 1.0931x; 1.0931x over previous
#include <cuda_runtime.h>
#include <cstdint>

#define NB       4
#define NN       2048
#define CLAMP_V  10.0f

typedef unsigned long long ull;

// Partial G (4 d-quarters): [4][NB*NN][32] floats = 4 MB (no allocs allowed)
__device__ __align__(16) float g_Gp[4 * NB * NN * 32];
// Reduced G + row squared-norms
__device__ __align__(16) float g_G[NB * NN * 32];
__device__ __align__(16) float g_Gsq[NB * NN];

// ---------------- packed f32x2 helpers (FFMA2 via PTX) ----------------
__device__ __forceinline__ ull ffma2(ull a, ull b, ull c) {
    ull d;
    asm("fma.rn.f32x2 %0, %1, %2, %3;" : "=l"(d) : "l"(a), "l"(b), "l"(c));
    return d;
}
__device__ __forceinline__ ull pack2(float x, float y) {
    ull r;
    asm("mov.b64 %0, {%1, %2};" : "=l"(r) : "f"(x), "f"(y));
    return r;
}
__device__ __forceinline__ float2 unpack2(ull v) {
    float2 f;
    asm("mov.b64 {%0, %1}, %2;" : "=f"(f.x), "=f"(f.y) : "l"(v));
    return f;
}
__device__ __forceinline__ float hadd2(ull v) {
    float2 f = unpack2(v);
    return f.x + f.y;
}
__device__ __forceinline__ uint32_t smem_u32(const void* p) {
    uint32_t a;
    asm("{ .reg .u64 t; cvta.to.shared.u64 t, %1; cvt.u32.u64 %0, t; }" : "=r"(a) : "l"(p));
    return a;
}
__device__ __forceinline__ void cp16(uint32_t dst, const void* src) {
    asm volatile("cp.async.cg.shared.global [%0], [%1], 16;" :: "r"(dst), "l"(src) : "memory");
}
#define CP_COMMIT() asm volatile("cp.async.commit_group;" ::: "memory")
#define CP_WAIT0()  asm volatile("cp.async.wait_group 0;" ::: "memory")

// ============================================================================
// Kernel 1: partial G[q][n][k] = sum_{d in quarter q} H[n][d] * W[k][d]
// 256 blocks (64 row-tiles x 4 d-quarters) x 256 threads; micro 4 rows x 4 k.
// SINGLE barrier per chunk: store Ws[buf] -> cp.wait -> sync -> prefetch ->
// compute.  (Ws store overlaps the cp.async drain; prefetch-after-sync keeps
// the double-buffer hazard-free.)
// ============================================================================
#define HROW 18   // ull per H row (16 dpairs + pad 2)
#define WROW 34   // ull per Ws row (32 k + pad 2)

__global__ __launch_bounds__(256)
void geom_proj_kernel(const float* __restrict__ H, const float* __restrict__ W) {
    __shared__ ull Hs[2][128][HROW];
    __shared__ ull Ws[2][16][WROW];

    const int tid  = threadIdx.x;
    const int kg   = tid & 7;          // k = kg + 8q
    const int ty   = tid >> 3;         // rows ty + 32*r  (0..31)
    const int quar = blockIdx.x & 3;
    const int n0   = (blockIdx.x >> 2) * 128;
    const int dbase = quar * 256;      // float offset

    const float4* __restrict__ W4 = (const float4*)W;
    const uint32_t hsb = smem_u32(&Hs[0][0][0]);

    // ---- prologue: cp.async H chunk 0, LDG W chunk 0
    #pragma unroll
    for (int p = 0; p < 4; p++) {
        int idx = tid + 256 * p;       // 0..1023
        int row = idx >> 3, fc = idx & 7;
        cp16(hsb + (uint32_t)(row * HROW + fc * 2) * 8,
             H + (size_t)(n0 + row) * 1024 + dbase + fc * 4);
    }
    CP_COMMIT();

    float4 wr = W4[(tid >> 3) * 256 + quar * 64 + (tid & 7)];

    ull acc[4][4];
    #pragma unroll
    for (int r = 0; r < 4; r++)
        #pragma unroll
        for (int q = 0; q < 4; q++) acc[r][q] = 0ULL;

    #pragma unroll 1
    for (int c = 0; c < 8; c++) {
        const int buf = c & 1;

        // stage W chunk c into Ws[buf] (overlaps the cp.async completion;
        // last readers of Ws[buf] were at iter c-2, fenced by iter c-1's sync)
        {
            int k = tid >> 3, fs = tid & 7;
            Ws[buf][fs * 2][k]     = pack2(wr.x, wr.y);
            Ws[buf][fs * 2 + 1][k] = pack2(wr.z, wr.w);
        }

        CP_WAIT0();                    // H chunk c resident
        __syncthreads();               // the ONLY barrier this chunk

        if (c < 7) {                   // prefetch chunk c+1 (after the sync:
                                       // iter c-1 readers of Hs[1-buf] have
                                       // all passed this barrier)
            #pragma unroll
            for (int p = 0; p < 4; p++) {
                int idx = tid + 256 * p;
                int row = idx >> 3, fc = idx & 7;
                cp16(hsb + (uint32_t)(((1 - buf) * 128 + row) * HROW + fc * 2) * 8,
                     H + (size_t)(n0 + row) * 1024 + dbase + (c + 1) * 32 + fc * 4);
            }
            CP_COMMIT();
            wr = W4[(tid >> 3) * 256 + quar * 64 + (c + 1) * 8 + (tid & 7)];
        }

        #pragma unroll
        for (int dp2 = 0; dp2 < 8; dp2++) {
            ull w0[4], w1[4];
            #pragma unroll
            for (int q = 0; q < 4; q++) {
                w0[q] = Ws[buf][2 * dp2][kg + 8 * q];
                w1[q] = Ws[buf][2 * dp2 + 1][kg + 8 * q];
            }
            #pragma unroll
            for (int r = 0; r < 4; r++) {
                float4 hv = *(const float4*)&Hs[buf][ty + 32 * r][2 * dp2];
                ull hA = pack2(hv.x, hv.y);
                ull hB = pack2(hv.z, hv.w);
                #pragma unroll
                for (int q = 0; q < 4; q++) {
                    acc[r][q] = ffma2(hA, w0[q], acc[r][q]);
                    acc[r][q] = ffma2(hB, w1[q], acc[r][q]);
                }
            }
        }
    }

    float* __restrict__ Gp = g_Gp + (size_t)quar * (NB * NN * 32);
    #pragma unroll
    for (int r = 0; r < 4; r++) {
        const size_t rb = (size_t)(n0 + ty + 32 * r) * 32;
        #pragma unroll
        for (int q = 0; q < 4; q++)
            Gp[rb + kg + 8 * q] = hadd2(acc[r][q]);
    }
}

// ============================================================================
// Kernel 1.5: reduce the 4 d-quarter partials -> g_G, and compute g_Gsq.
// ============================================================================
__global__ __launch_bounds__(128)
void reduce_g_kernel() {
    const int tid = threadIdx.x;
    const int row = blockIdx.x * 32 + (tid >> 2);   // global row 0..8191
    const int fq  = tid & 3;

    const float4* __restrict__ P0 = (const float4*)g_Gp;
    const float4* __restrict__ P1 = P0 + (NB * NN * 32) / 4;
    const float4* __restrict__ P2 = P1 + (NB * NN * 32) / 4;
    const float4* __restrict__ P3 = P2 + (NB * NN * 32) / 4;
    float4* __restrict__ Go = (float4*)g_G;

    float sq = 0.f;
    #pragma unroll
    for (int h = 0; h < 2; h++) {
        const size_t idx = (size_t)row * 8 + fq + 4 * h;
        float4 a0 = P0[idx];
        float4 a1 = P1[idx];
        float4 a2 = P2[idx];
        float4 a3 = P3[idx];
        float4 s;
        s.x = (a0.x + a1.x) + (a2.x + a3.x);
        s.y = (a0.y + a1.y) + (a2.y + a3.y);
        s.z = (a0.z + a1.z) + (a2.z + a3.z);
        s.w = (a0.w + a1.w) + (a2.w + a3.w);
        Go[idx] = s;
        sq += s.x * s.x + s.y * s.y + s.z * s.z + s.w * s.w;
    }
    sq += __shfl_xor_sync(0xFFFFFFFF, sq, 1);
    sq += __shfl_xor_sync(0xFFFFFFFF, sq, 2);
    if (fq == 0) g_Gsq[row] = sq;
}

// ============================================================================
// Kernel 2: triangular-symmetric EMA update (R13 best structure) with
// register double-buffered b-operands in the Gram loop.
// Grid (528, 4); 128 threads; 64x64 tile; Gram micro 8(i) x 4(j).
// ============================================================================
#define GROW 18    // 16 kpairs + pad 2

__global__ __launch_bounds__(128, 3)
void bias_update_kernel(const float* __restrict__ Bprev,
                        const float* __restrict__ alpha_p,
                        const float* __restrict__ beta_p,
                        float* __restrict__ Out) {
    __shared__ __align__(16) unsigned char gbuf[2][9216];  // Gi | Gj; later dist_t
    __shared__ __align__(16) float dist_s[64][68];
    __shared__ float gsqI[64];
    __shared__ float gsqJ[64];

    ull (*Gi)[GROW] = (ull(*)[GROW])gbuf[0];
    ull (*Gj)[GROW] = (ull(*)[GROW])gbuf[1];
    float (*dist_t)[68] = (float(*)[68])gbuf;              // 64*68*4 = 17408 <= 18432

    const int tid = threadIdx.x;
    const int tx  = tid & 15;      // Gram: j = tx + 16*jj
    const int ty  = tid >> 4;      // Gram: i = ty + 8*ii
    const int b   = blockIdx.y;

    // triangular decode: q -> (ti, tj), tj <= ti
    const int q = blockIdx.x;
    int ti = (int)((sqrtf(8.0f * (float)q + 1.0f) - 1.0f) * 0.5f);
    while ((ti + 1) * (ti + 2) / 2 <= q) ti++;
    while (ti * (ti + 1) / 2 > q) ti--;
    const int tj = q - ti * (ti + 1) / 2;
    const int i0 = ti * 64;
    const int j0 = tj * 64;
    const bool offd = (ti != tj);

    // ---- stage G tiles (single reduced source) + precomputed Gsq
    const float4* __restrict__ G4 = (const float4*)g_G;
    const size_t baseI = ((size_t)b * NN + i0) * 8;   // float4 units (8/row)
    const size_t baseJ = ((size_t)b * NN + j0) * 8;

    #pragma unroll
    for (int p = 0; p < 4; p++) {
        int idx = tid + 128 * p;               // 0..511
        int row = idx >> 3, fc = idx & 7;
        float4 a = G4[baseI + idx];
        *(float4*)&Gi[row][fc * 2] = a;
        float4 c = G4[baseJ + idx];
        *(float4*)&Gj[row][fc * 2] = c;
    }
    if (tid < 64)       gsqI[tid]      = g_Gsq[(size_t)b * NN + i0 + tid];
    else                gsqJ[tid - 64] = g_Gsq[(size_t)b * NN + j0 + (tid - 64)];
    __syncthreads();

    // ---- 8x4 Gram micro-tile; b-operands double-buffered in registers
    ull acc[8][4];
    #pragma unroll
    for (int ii = 0; ii < 8; ii++)
        #pragma unroll
        for (int jj = 0; jj < 4; jj++) acc[ii][jj] = 0ULL;

    ull b0[2][4], b1[2][4];
    #pragma unroll
    for (int jj = 0; jj < 4; jj++) {
        float4 t = *(const float4*)&Gj[tx + 16 * jj][0];
        b0[0][jj] = pack2(t.x, t.y);
        b1[0][jj] = pack2(t.z, t.w);
    }

    #pragma unroll
    for (int kk2 = 0; kk2 < 8; kk2++) {
        const int cur = kk2 & 1;
        if (kk2 < 7) {                 // prefetch next kk2's b-operands
            #pragma unroll
            for (int jj = 0; jj < 4; jj++) {
                float4 t = *(const float4*)&Gj[tx + 16 * jj][(kk2 + 1) * 2];
                b0[cur ^ 1][jj] = pack2(t.x, t.y);
                b1[cur ^ 1][jj] = pack2(t.z, t.w);
            }
        }
        ull a0[8], a1[8];
        #pragma unroll
        for (int ii = 0; ii < 8; ii++) {
            float4 t = *(const float4*)&Gi[ty + 8 * ii][kk2 * 2];
            a0[ii] = pack2(t.x, t.y);
            a1[ii] = pack2(t.z, t.w);
        }
        #pragma unroll
        for (int ii = 0; ii < 8; ii++)
            #pragma unroll
            for (int jj = 0; jj < 4; jj++) {
                acc[ii][jj] = ffma2(a0[ii], b0[cur][jj], acc[ii][jj]);
                acc[ii][jj] = ffma2(a1[ii], b1[cur][jj], acc[ii][jj]);
            }
    }

    const float alpha = __ldg(alpha_p);
    const float beta  = __ldg(beta_p);

    // ---- Phase B: bd = beta*max(dist,0) into registers
    float bd[8][4];
    #pragma unroll
    for (int ii = 0; ii < 8; ii++) {
        const float si = gsqI[ty + 8 * ii];
        #pragma unroll
        for (int jj = 0; jj < 4; jj++) {
            float g = hadd2(acc[ii][jj]);
            float dist = si + gsqJ[tx + 16 * jj] - 2.0f * g;
            bd[ii][jj] = beta * fmaxf(dist, 0.0f);
        }
    }
    __syncthreads();               // all Gram smem reads done (dist_t aliases G)

    #pragma unroll
    for (int ii = 0; ii < 8; ii++) {
        const int il = ty + 8 * ii;
        #pragma unroll
        for (int jj = 0; jj < 4; jj++) {
            const int jl = tx + 16 * jj;
            dist_s[il][jl] = bd[ii][jj];
            if (offd) dist_t[jl][il] = bd[ii][jj];
        }
    }
    __syncthreads();

    // ---- Phase C: vectorized epilogue; all loads batched (MLP up to 16)
    const int c4 = tid & 15;       // float4 column
    const int rg = tid >> 4;       // row = rg + 8*rr
    const size_t obase = (size_t)b * NN * NN;

    float4 bp1[8], bp2[8];
    #pragma unroll
    for (int rr = 0; rr < 8; rr++) {
        const int row = rg + 8 * rr;
        bp1[rr] = __ldg((const float4*)(Bprev + obase + (size_t)(i0 + row) * NN + j0 + 4 * c4));
    }
    if (offd) {
        #pragma unroll
        for (int rr = 0; rr < 8; rr++) {
            const int row = rg + 8 * rr;
            bp2[rr] = __ldg((const float4*)(Bprev + obase + (size_t)(j0 + row) * NN + i0 + 4 * c4));
        }
    }

    #pragma unroll
    for (int rr = 0; rr < 8; rr++) {
        const int row = rg + 8 * rr;
        float4 d = *(const float4*)&dist_s[row][4 * c4];
        float4 v;
        v.x = fminf(fmaxf(fmaf(alpha, bp1[rr].x, -d.x), -CLAMP_V), CLAMP_V);
        v.y = fminf(fmaxf(fmaf(alpha, bp1[rr].y, -d.y), -CLAMP_V), CLAMP_V);
        v.z = fminf(fmaxf(fmaf(alpha, bp1[rr].z, -d.z), -CLAMP_V), CLAMP_V);
        v.w = fminf(fmaxf(fmaf(alpha, bp1[rr].w, -d.w), -CLAMP_V), CLAMP_V);
        *(float4*)(Out + obase + (size_t)(i0 + row) * NN + j0 + 4 * c4) = v;
    }
    if (offd) {
        #pragma unroll
        for (int rr = 0; rr < 8; rr++) {
            const int row = rg + 8 * rr;
            float4 d = *(const float4*)&dist_t[row][4 * c4];
            float4 v;
            v.x = fminf(fmaxf(fmaf(alpha, bp2[rr].x, -d.x), -CLAMP_V), CLAMP_V);
            v.y = fminf(fmaxf(fmaf(alpha, bp2[rr].y, -d.y), -CLAMP_V), CLAMP_V);
            v.z = fminf(fmaxf(fmaf(alpha, bp2[rr].z, -d.z), -CLAMP_V), CLAMP_V);
            v.w = fminf(fmaxf(fmaf(alpha, bp2[rr].w, -d.w), -CLAMP_V), CLAMP_V);
            *(float4*)(Out + obase + (size_t)(j0 + row) * NN + i0 + 4 * c4) = v;
        }
    }
}

// ============================================================================
extern "C" void kernel_launch(void* const* d_in, const int* in_sizes, int n_in,
                              void* d_out, int out_size) {
    const float* H     = (const float*)d_in[0];   // [4,2048,1024]
    const float* Bprev = (const float*)d_in[1];   // [4,2048,2048]
    const float* W     = (const float*)d_in[2];   // [32,1024]
    const float* alpha = (const float*)d_in[3];   // scalar
    const float* beta  = (const float*)d_in[4];   // scalar
    float* Out = (float*)d_out;

    geom_proj_kernel<<<256, 256>>>(H, W);
    reduce_g_kernel<<<256, 128>>>();
    bias_update_kernel<<<dim3(528, NB), 128>>>(Bprev, alpha, beta, Out);
}